// round 15
// baseline (speedup 1.0000x reference)
#include <cuda_runtime.h>
#include <cstdint>

#define FEAT  4096
#define BATCH 2048
#define GUARD 128
#define KP_N  (GUARD + FEAT)              // 4224 tf32 pairs

// ---- dynamic SMEM layout (bytes) ----
#define KP_OFF  0                          // 4224 * 8 = 33792 B
#define A_OFF   33792                      // 128-aligned; 2 superbufs x 32768 B
#define A_BYTES 32768                      // 128 rows x 64 cols fp32 (two 16KB halves)
#define SMEM_TOTAL (A_OFF + 2 * A_BYTES)   // 99328 B -> 2 CTAs/SM

__device__ __forceinline__ uint32_t smem_u32(const void* p) {
    uint32_t a;
    asm("{ .reg .u64 t; cvta.to.shared.u64 t, %1; cvt.u32.u64 %0, t; }" : "=r"(a) : "l"(p));
    return a;
}
__device__ __forceinline__ uint32_t f2tf32(float f) {
    uint32_t u;
    asm("cvt.rna.tf32.f32 %0, %1;" : "=r"(u) : "f"(f));
    return u;
}
__device__ __forceinline__ void mma_tf32(float* c, const uint32_t* a, uint32_t b0, uint32_t b1) {
    asm volatile(
        "mma.sync.aligned.m16n8k8.row.col.f32.tf32.tf32.f32 "
        "{%0,%1,%2,%3}, {%4,%5,%6,%7}, {%8,%9}, {%0,%1,%2,%3};"
        : "+f"(c[0]), "+f"(c[1]), "+f"(c[2]), "+f"(c[3])
        : "r"(a[0]), "r"(a[1]), "r"(a[2]), "r"(a[3]), "r"(b0), "r"(b1));
}
__device__ __forceinline__ void ldsm_x4(uint32_t* r, uint32_t addr) {
    asm volatile("ldmatrix.sync.aligned.m8n8.x4.shared.b16 {%0,%1,%2,%3}, [%4];"
        : "=r"(r[0]), "=r"(r[1]), "=r"(r[2]), "=r"(r[3]) : "r"(addr));
}
__device__ __forceinline__ void lds_pair(uint32_t& p0, uint32_t& p1, uint32_t addr) {
    asm volatile("ld.shared.v2.b32 {%0,%1}, [%2];" : "=r"(p0), "=r"(p1) : "r"(addr));
}
#define CP_ASYNC16(dst, src) \
    asm volatile("cp.async.cg.shared.global [%0], [%1], 16;" :: "r"(dst), "l"(src) : "memory")
#define CP_COMMIT()  asm volatile("cp.async.commit_group;" ::: "memory")
#define CP_WAIT(n)   asm volatile("cp.async.wait_group %0;" :: "n"(n) : "memory")

__global__ __launch_bounds__(256, 2)
void toep_mma7(const float* __restrict__ x, const float* __restrict__ kern,
               float* __restrict__ out)
{
    extern __shared__ __align__(128) char smem[];
    uint32_t* kpw = (uint32_t*)(smem + KP_OFF);     // pair table: kp[i] = words 2i, 2i+1

    const int tid  = threadIdx.x;
    const int wid  = tid >> 5, lane = tid & 31;
    const int g    = lane >> 2, tg = lane & 3;

    const int bx = (int)blockIdx.x;                 // tile pair (31-bx, bx)
    const int b0 = (int)blockIdx.y << 7;

    // warp tile: 32(m) x 64(n); 4 m-warps x 2 n-warps
    const int m0 = (wid & 3) << 5;
    const int n0 = (wid >> 2) << 6;

    // ---- build kp[i] = (tf32(kern[i-G]), tf32(kern[i-G-4])), zeros under guard ----
    for (int i = tid; i < KP_N; i += 256) {
        kpw[2 * i] = 0u; kpw[2 * i + 1] = 0u;
    }
    __syncthreads();
    for (int i = tid; i < FEAT; i += 256) {
        const uint32_t u = f2tf32(kern[i]);
        kpw[2 * (GUARD + i)] = u;                    // kp[G+i].x
        if (i < FEAT - 4) kpw[2 * (GUARD + i + 4) + 1] = u;  // kp[G+i+4].y
    }

    // ---- A staging params ----
    const int arow = tid >> 1;
    const int aq0  = (tid & 1) << 2;
    const float* xrow = x + (size_t)(b0 + arow) * FEAT;
    const uint32_t asw = (uint32_t)((arow & 7) << 2);
    const uint32_t abase = smem_u32(smem + A_OFF);
    const uint32_t kpb = smem_u32(smem + KP_OFF);

    __syncthreads();                                  // kp table visible

    // ldmatrix lane addressing
    const int lrow = lane & 15;
    const int c0l  = (lane < 16) ? 0 : 4;
    int rbase[2], swl[2];
    #pragma unroll
    for (int mf = 0; mf < 2; ++mf) {
        const int rf = m0 + (mf << 4) + lrow;
        rbase[mf] = rf << 5;
        swl[mf]   = (rf & 7) << 2;
    }

    // ---- continuous superchunk stream over both tiles of the pair ----
    const int it0  = 31 - bx;                         // heavy tile first
    const int i00  = it0 << 7;
    const int i01  = bx << 7;
    const int nsc0 = (it0 + 1) << 1;                  // 34..64
    const int NSC  = 66;                              // nsc0 + nsc1, constant for all CTAs

    // stream s -> k column: tile0 cols s<<6, tile1 cols (s-nsc0)<<6
    auto issue = [&](int s) {
        const uint32_t dstb = abase + (uint32_t)((s & 1) ? A_BYTES : 0);
        const int col = (s < nsc0) ? (s << 6) : ((s - nsc0) << 6);
        const float* srcb = xrow + col;
        #pragma unroll
        for (int h = 0; h < 2; ++h)
            #pragma unroll
            for (int q = 0; q < 4; ++q) {
                const uint32_t c4 = (uint32_t)((aq0 + q) << 2);
                const uint32_t w  = (uint32_t)(arow << 5) + (c4 ^ asw);
                CP_ASYNC16(dstb + (uint32_t)(h << 14) + (w << 2), srcb + (h << 5) + c4);
            }
    };

    issue(0); CP_COMMIT();

    // B circular registers from pair table: w = (nf - T) & 7
    int bptr = GUARD + i00 + n0 + g - tg;
    uint32_t bv0[8], bv1[8];
    #pragma unroll
    for (int w = 0; w < 8; ++w)
        lds_pair(bv0[w], bv1[w], kpb + (uint32_t)((bptr + (w << 3)) << 3));

    float acc[2][8][4];
    #pragma unroll
    for (int mf = 0; mf < 2; ++mf)
        #pragma unroll
        for (int nf = 0; nf < 8; ++nf)
            #pragma unroll
            for (int r = 0; r < 4; ++r) acc[mf][nf][r] = 0.0f;

    // epilogue: write acc for tile at i0, then zero acc
    auto epilogue = [&](int i0) {
        #pragma unroll
        for (int mf = 0; mf < 2; ++mf) {
            const int row = b0 + m0 + (mf << 4) + g;
            float* o0 = out + (size_t)row * FEAT + i0 + n0 + (tg << 1);
            float* o1 = o0 + 8 * FEAT;
            #pragma unroll
            for (int nf = 0; nf < 8; ++nf) {
                *(float2*)(o0 + (nf << 3)) = make_float2(acc[mf][nf][0], acc[mf][nf][1]);
                *(float2*)(o1 + (nf << 3)) = make_float2(acc[mf][nf][2], acc[mf][nf][3]);
                acc[mf][nf][0] = 0.0f; acc[mf][nf][1] = 0.0f;
                acc[mf][nf][2] = 0.0f; acc[mf][nf][3] = 0.0f;
            }
        }
    };

    for (int s = 0; s < NSC; ++s) {
        CP_WAIT(0);                                   // stream s landed
        __syncthreads();                              // visible; other buffer free
        if (s + 1 < NSC) { issue(s + 1); }            // next stream fills other buffer
        CP_COMMIT();

        if (s == nsc0) {                              // tile boundary: pipeline keeps flowing
            epilogue(i00);                            // overlaps in-flight cp.async
            bptr = GUARD + i01 + n0 + g - tg;         // reload B ring for tile1
            #pragma unroll
            for (int w = 0; w < 8; ++w)
                lds_pair(bv0[w], bv1[w], kpb + (uint32_t)((bptr + (w << 3)) << 3));
        }

        const uint32_t bufb = abase + (uint32_t)((s & 1) ? A_BYTES : 0);

        // software-pipelined A fragments: parity-indexed, zero-mov unrolled
        uint32_t a[2][2][4];
        {
            const int u0 = c0l;                       // T = 0 (half h=0)
            ldsm_x4(a[0][0], bufb + (uint32_t)((rbase[0] + (u0 ^ swl[0])) << 2));
            ldsm_x4(a[0][1], bufb + (uint32_t)((rbase[1] + (u0 ^ swl[1])) << 2));
        }
        #pragma unroll
        for (int T = 0; T < 8; ++T) {
            const int p = T & 1;
            if (T < 7) {                              // prefetch T+1 fragments
                const uint32_t hb = bufb + (uint32_t)((((T + 1) >> 2) & 1) << 14);
                const int u = (((T + 1) & 3) << 3) | c0l;
                ldsm_x4(a[p ^ 1][0], hb + (uint32_t)((rbase[0] + (u ^ swl[0])) << 2));
                ldsm_x4(a[p ^ 1][1], hb + (uint32_t)((rbase[1] + (u ^ swl[1])) << 2));
            }
            #pragma unroll
            for (int nf = 0; nf < 8; ++nf) {
                const int w = (nf - T) & 7;
                mma_tf32(acc[0][nf], a[p][0], bv0[w], bv1[w]);
                mma_tf32(acc[1][nf], a[p][1], bv0[w], bv1[w]);
            }
            const int wr = (7 - T) & 7;               // refill slot consumed 8 steps later
            lds_pair(bv0[wr], bv1[wr], kpb + (uint32_t)((bptr - 8) << 3));
            bptr -= 8;
        }
    }
    CP_WAIT(0);

    epilogue(i01);                                    // tile1 results
}

extern "C" void kernel_launch(void* const* d_in, const int* in_sizes, int n_in,
                              void* d_out, int out_size)
{
    const float* x    = (const float*)d_in[0];   // [2048, 4096] fp32
    const float* kern = (const float*)d_in[1];   // [4096] fp32
    float* out = (float*)d_out;                  // [2048, 4096] fp32

    cudaFuncSetAttribute(toep_mma7, cudaFuncAttributeMaxDynamicSharedMemorySize, SMEM_TOTAL);
    dim3 grid(16, 16);                           // 16 balanced tile-pairs x 16 batch tiles
    toep_mma7<<<grid, 256, SMEM_TOTAL>>>(x, kern, out);
}

// round 16
// speedup vs baseline: 1.1433x; 1.1433x over previous
#include <cuda_runtime.h>
#include <cstdint>

#define FEAT  4096
#define BATCH 2048
#define GUARD 128
#define KP_N  (GUARD + FEAT)              // 4224 tf32 pairs

// ---- dynamic SMEM layout (bytes) ----
#define KP_OFF  0                          // 4224 * 8 = 33792 B
#define A_OFF   33792                      // per CTA-half: 2 stages x 16384 B
#define H_BYTES 32768                      // one half's ring (2 stages)
#define STG_BYTES 16384                    // 64 rows x 64 cols fp32 (two 8KB col-halves)
#define SMEM_TOTAL (A_OFF + 2 * H_BYTES)   // 99328 B -> 2 CTAs/SM

__device__ __forceinline__ uint32_t smem_u32(const void* p) {
    uint32_t a;
    asm("{ .reg .u64 t; cvta.to.shared.u64 t, %1; cvt.u32.u64 %0, t; }" : "=r"(a) : "l"(p));
    return a;
}
__device__ __forceinline__ uint32_t f2tf32(float f) {
    uint32_t u;
    asm("cvt.rna.tf32.f32 %0, %1;" : "=r"(u) : "f"(f));
    return u;
}
__device__ __forceinline__ void mma_tf32(float* c, const uint32_t* a, uint32_t b0, uint32_t b1) {
    asm volatile(
        "mma.sync.aligned.m16n8k8.row.col.f32.tf32.tf32.f32 "
        "{%0,%1,%2,%3}, {%4,%5,%6,%7}, {%8,%9}, {%0,%1,%2,%3};"
        : "+f"(c[0]), "+f"(c[1]), "+f"(c[2]), "+f"(c[3])
        : "r"(a[0]), "r"(a[1]), "r"(a[2]), "r"(a[3]), "r"(b0), "r"(b1));
}
__device__ __forceinline__ void ldsm_x4(uint32_t* r, uint32_t addr) {
    asm volatile("ldmatrix.sync.aligned.m8n8.x4.shared.b16 {%0,%1,%2,%3}, [%4];"
        : "=r"(r[0]), "=r"(r[1]), "=r"(r[2]), "=r"(r[3]) : "r"(addr));
}
__device__ __forceinline__ void lds_pair(uint32_t& p0, uint32_t& p1, uint32_t addr) {
    asm volatile("ld.shared.v2.b32 {%0,%1}, [%2];" : "=r"(p0), "=r"(p1) : "r"(addr));
}
#define CP_ASYNC16(dst, src) \
    asm volatile("cp.async.cg.shared.global [%0], [%1], 16;" :: "r"(dst), "l"(src) : "memory")
#define CP_COMMIT()  asm volatile("cp.async.commit_group;" ::: "memory")
#define CP_WAIT(n)   asm volatile("cp.async.wait_group %0;" :: "n"(n) : "memory")
#define BARH(id)     asm volatile("bar.sync %0, 128;" :: "r"(id) : "memory")

__global__ __launch_bounds__(256, 2)
void toep_mma8(const float* __restrict__ x, const float* __restrict__ kern,
               float* __restrict__ out)
{
    extern __shared__ __align__(128) char smem[];
    uint32_t* kpw = (uint32_t*)(smem + KP_OFF);     // pair table: kp[i] = words 2i, 2i+1

    const int tid  = threadIdx.x;
    const int half = tid >> 7;                      // independent CTA half (0/1)
    const int htid = tid & 127;
    const int hwid = htid >> 5, lane = htid & 31;
    const int g    = lane >> 2, tg = lane & 3;
    const int barid = 1 + half;                     // named barrier per half

    const int bx = (int)blockIdx.x;                 // tile pair (31-bx, bx)
    const int b0 = (int)blockIdx.y << 7;

    // half-warp layout: 2 m-warps x 2 n-warps over 64(m) x 128(n)
    const int m0h = (hwid & 1) << 5;                // rows within half: 0 or 32
    const int n0  = (hwid >> 1) << 6;               // 0 or 64

    // ---- build kp[i] = (tf32(kern[i-G]), tf32(kern[i-G-4])), zeros under guard ----
    for (int i = tid; i < KP_N; i += 256) {
        kpw[2 * i] = 0u; kpw[2 * i + 1] = 0u;
    }
    __syncthreads();
    for (int i = tid; i < FEAT; i += 256) {
        const uint32_t u = f2tf32(kern[i]);
        kpw[2 * (GUARD + i)] = u;                    // kp[G+i].x
        if (i < FEAT - 4) kpw[2 * (GUARD + i + 4) + 1] = u;  // kp[G+i+4].y
    }

    // ---- A staging params (per half: 64 rows x 64 cols per superchunk) ----
    const int arow = htid >> 1;                      // 0..63
    const int aq0  = (htid & 1) << 2;
    const float* xrow = x + (size_t)(b0 + (half << 6) + arow) * FEAT;
    const uint32_t asw = (uint32_t)((arow & 7) << 2);
    const uint32_t habase = smem_u32(smem + A_OFF) + (uint32_t)(half * H_BYTES);
    const uint32_t kpb = smem_u32(smem + KP_OFF);

    __syncthreads();                                  // kp table visible; last full-CTA sync

    // ldmatrix lane addressing (rows relative to half buffer)
    const int lrow = lane & 15;
    const int c0l  = (lane < 16) ? 0 : 4;
    int rbase[2], swl[2];
    #pragma unroll
    for (int mf = 0; mf < 2; ++mf) {
        const int rf = m0h + (mf << 4) + lrow;
        rbase[mf] = rf << 5;                          // row stride = 32 words per col-half
        swl[mf]   = (rf & 7) << 2;
    }

    for (int tp = 0; tp < 2; ++tp) {
        const int it = tp ? bx : 31 - bx;             // heavy tile first
        const int i0 = it << 7;
        const int nsc = (it + 1) << 1;                // superchunks of 64 k, >= 2

        auto issue = [&](int sc) {
            const uint32_t dstb = habase + (uint32_t)((sc & 1) ? STG_BYTES : 0);
            const float* srcb = xrow + (sc << 6);
            #pragma unroll
            for (int h = 0; h < 2; ++h)               // two 32-col halves (8KB each)
                #pragma unroll
                for (int q = 0; q < 4; ++q) {
                    const uint32_t c4 = (uint32_t)((aq0 + q) << 2);
                    const uint32_t w  = (uint32_t)(arow << 5) + (c4 ^ asw);
                    CP_ASYNC16(dstb + (uint32_t)(h << 13) + (w << 2), srcb + (h << 5) + c4);
                }
        };

        if (tp) BARH(barid);                          // half's bufs free before refill
        issue(0); CP_COMMIT();

        // B circular registers from pair table: w = (nf - T) & 7
        int bptr = GUARD + i0 + n0 + g - tg;
        uint32_t bv0[8], bv1[8];
        #pragma unroll
        for (int w = 0; w < 8; ++w)
            lds_pair(bv0[w], bv1[w], kpb + (uint32_t)((bptr + (w << 3)) << 3));

        float acc[2][8][4];
        #pragma unroll
        for (int mf = 0; mf < 2; ++mf)
            #pragma unroll
            for (int nf = 0; nf < 8; ++nf)
                #pragma unroll
                for (int r = 0; r < 4; ++r) acc[mf][nf][r] = 0.0f;

        for (int sc = 0; sc < nsc; ++sc) {
            CP_WAIT(0);                               // half's superchunk sc landed
            BARH(barid);                              // visible to half; other stage free
            if (sc + 1 < nsc) { issue(sc + 1); }
            CP_COMMIT();

            const uint32_t bufb = habase + (uint32_t)((sc & 1) ? STG_BYTES : 0);

            // software-pipelined A fragments: parity-indexed, zero-mov unrolled
            uint32_t a[2][2][4];
            {
                const int u0 = c0l;                   // T = 0 (col-half 0)
                ldsm_x4(a[0][0], bufb + (uint32_t)((rbase[0] + (u0 ^ swl[0])) << 2));
                ldsm_x4(a[0][1], bufb + (uint32_t)((rbase[1] + (u0 ^ swl[1])) << 2));
            }
            #pragma unroll
            for (int T = 0; T < 8; ++T) {
                const int p = T & 1;
                if (T < 7) {                          // prefetch T+1 fragments
                    const uint32_t hb = bufb + (uint32_t)((((T + 1) >> 2) & 1) << 13);
                    const int u = (((T + 1) & 3) << 3) | c0l;
                    ldsm_x4(a[p ^ 1][0], hb + (uint32_t)((rbase[0] + (u ^ swl[0])) << 2));
                    ldsm_x4(a[p ^ 1][1], hb + (uint32_t)((rbase[1] + (u ^ swl[1])) << 2));
                }
                #pragma unroll
                for (int nf = 0; nf < 8; ++nf) {
                    const int w = (nf - T) & 7;
                    mma_tf32(acc[0][nf], a[p][0], bv0[w], bv1[w]);
                    mma_tf32(acc[1][nf], a[p][1], bv0[w], bv1[w]);
                }
                const int wr = (7 - T) & 7;           // refill slot consumed 8 steps later
                lds_pair(bv0[wr], bv1[wr], kpb + (uint32_t)((bptr - 8) << 3));
                bptr -= 8;
            }
        }
        CP_WAIT(0);

        // ---- epilogue for this tile (half-local rows) ----
        #pragma unroll
        for (int mf = 0; mf < 2; ++mf) {
            const int row = b0 + (half << 6) + m0h + (mf << 4) + g;
            float* o0 = out + (size_t)row * FEAT + i0 + n0 + (tg << 1);
            float* o1 = o0 + 8 * FEAT;
            #pragma unroll
            for (int nf = 0; nf < 8; ++nf) {
                *(float2*)(o0 + (nf << 3)) = make_float2(acc[mf][nf][0], acc[mf][nf][1]);
                *(float2*)(o1 + (nf << 3)) = make_float2(acc[mf][nf][2], acc[mf][nf][3]);
            }
        }
    }
}

extern "C" void kernel_launch(void* const* d_in, const int* in_sizes, int n_in,
                              void* d_out, int out_size)
{
    const float* x    = (const float*)d_in[0];   // [2048, 4096] fp32
    const float* kern = (const float*)d_in[1];   // [4096] fp32
    float* out = (float*)d_out;                  // [2048, 4096] fp32

    cudaFuncSetAttribute(toep_mma8, cudaFuncAttributeMaxDynamicSharedMemorySize, SMEM_TOTAL);
    dim3 grid(16, 16);                           // 16 balanced tile-pairs x 16 batch tiles
    toep_mma8<<<grid, 256, SMEM_TOTAL>>>(x, kern, out);
}

// round 17
// speedup vs baseline: 1.2631x; 1.1047x over previous
#include <cuda_runtime.h>
#include <cstdint>

#define FEAT  4096
#define BATCH 2048
#define GUARD 128
#define KP_N  (GUARD + FEAT)              // 4224 tf32 pairs

// ---- dynamic SMEM layout (bytes) ----
#define KP_OFF  0                          // 4224 * 8 = 33792 B
#define A_OFF   33792                      // per quarter: 2 stages x 8192 B
#define Q_BYTES 16384                      // one quarter's ring (2 stages)
#define STG_BYTES 8192                     // 32 rows x 64 cols fp32 (two 4KB col-halves)
#define SMEM_TOTAL (A_OFF + 4 * Q_BYTES)   // 99328 B -> 2 CTAs/SM

__device__ __forceinline__ uint32_t smem_u32(const void* p) {
    uint32_t a;
    asm("{ .reg .u64 t; cvta.to.shared.u64 t, %1; cvt.u32.u64 %0, t; }" : "=r"(a) : "l"(p));
    return a;
}
__device__ __forceinline__ uint32_t f2tf32(float f) {
    uint32_t u;
    asm("cvt.rna.tf32.f32 %0, %1;" : "=r"(u) : "f"(f));
    return u;
}
__device__ __forceinline__ void mma_tf32(float* c, const uint32_t* a, uint32_t b0, uint32_t b1) {
    asm volatile(
        "mma.sync.aligned.m16n8k8.row.col.f32.tf32.tf32.f32 "
        "{%0,%1,%2,%3}, {%4,%5,%6,%7}, {%8,%9}, {%0,%1,%2,%3};"
        : "+f"(c[0]), "+f"(c[1]), "+f"(c[2]), "+f"(c[3])
        : "r"(a[0]), "r"(a[1]), "r"(a[2]), "r"(a[3]), "r"(b0), "r"(b1));
}
__device__ __forceinline__ void ldsm_x4(uint32_t* r, uint32_t addr) {
    asm volatile("ldmatrix.sync.aligned.m8n8.x4.shared.b16 {%0,%1,%2,%3}, [%4];"
        : "=r"(r[0]), "=r"(r[1]), "=r"(r[2]), "=r"(r[3]) : "r"(addr));
}
__device__ __forceinline__ void lds_pair(uint32_t& p0, uint32_t& p1, uint32_t addr) {
    asm volatile("ld.shared.v2.b32 {%0,%1}, [%2];" : "=r"(p0), "=r"(p1) : "r"(addr));
}
#define CP_ASYNC16(dst, src) \
    asm volatile("cp.async.cg.shared.global [%0], [%1], 16;" :: "r"(dst), "l"(src) : "memory")
#define CP_COMMIT()  asm volatile("cp.async.commit_group;" ::: "memory")
#define CP_WAIT(n)   asm volatile("cp.async.wait_group %0;" :: "n"(n) : "memory")
#define BARQ(id)     asm volatile("bar.sync %0, 64;" :: "r"(id) : "memory")

__global__ __launch_bounds__(256, 2)
void toep_mma9(const float* __restrict__ x, const float* __restrict__ kern,
               float* __restrict__ out)
{
    extern __shared__ __align__(128) char smem[];
    uint32_t* kpw = (uint32_t*)(smem + KP_OFF);     // pair table: kp[i] = words 2i, 2i+1

    const int tid  = threadIdx.x;
    const int q    = tid >> 6;                      // independent quarter (0..3)
    const int qtid = tid & 63;
    const int lane = qtid & 31;
    const int g    = lane >> 2, tg = lane & 3;
    const int barid = 1 + q;                        // named barrier per quarter

    const int bx = (int)blockIdx.x;                 // tile pair (31-bx, bx)
    const int b0 = (int)blockIdx.y << 7;

    // quarter layout: 2 n-warps over 32(m) x 128(n); each warp 32m x 64n
    const int n0 = (qtid >> 5) << 6;                // 0 or 64

    // ---- build kp[i] = (tf32(kern[i-G]), tf32(kern[i-G-4])), zeros under guard ----
    for (int i = tid; i < KP_N; i += 256) {
        kpw[2 * i] = 0u; kpw[2 * i + 1] = 0u;
    }
    __syncthreads();
    for (int i = tid; i < FEAT; i += 256) {
        const uint32_t u = f2tf32(kern[i]);
        kpw[2 * (GUARD + i)] = u;                    // kp[G+i].x
        if (i < FEAT - 4) kpw[2 * (GUARD + i + 4) + 1] = u;  // kp[G+i+4].y
    }

    // ---- A staging params (per quarter: 32 rows x 64 cols per superchunk) ----
    const int arow = qtid >> 1;                      // 0..31
    const int aq0  = (qtid & 1) << 2;
    const float* xrow = x + (size_t)(b0 + (q << 5) + arow) * FEAT;
    const uint32_t asw = (uint32_t)((arow & 7) << 2);
    const uint32_t qabase = smem_u32(smem + A_OFF) + (uint32_t)(q * Q_BYTES);
    const uint32_t kpb = smem_u32(smem + KP_OFF);

    __syncthreads();                                  // kp table visible; last full-CTA sync

    // ldmatrix lane addressing (rows local to quarter buffer, 0..31)
    const int lrow = lane & 15;
    const int c0l  = (lane < 16) ? 0 : 4;
    int rbase[2], swl[2];
    #pragma unroll
    for (int mf = 0; mf < 2; ++mf) {
        const int rf = (mf << 4) + lrow;
        rbase[mf] = rf << 5;                          // 32-word rows per col-half
        swl[mf]   = (rf & 7) << 2;
    }

    for (int tp = 0; tp < 2; ++tp) {
        const int it = tp ? bx : 31 - bx;             // heavy tile first
        const int i0 = it << 7;
        const int nsc = (it + 1) << 1;                // superchunks of 64 k, >= 2

        auto issue = [&](int sc) {
            const uint32_t dstb = qabase + (uint32_t)((sc & 1) ? STG_BYTES : 0);
            const float* srcb = xrow + (sc << 6);
            #pragma unroll
            for (int h = 0; h < 2; ++h)               // two 32-col halves (4KB each)
                #pragma unroll
                for (int qq = 0; qq < 4; ++qq) {
                    const uint32_t c4 = (uint32_t)((aq0 + qq) << 2);
                    const uint32_t w  = (uint32_t)(arow << 5) + (c4 ^ asw);
                    CP_ASYNC16(dstb + (uint32_t)(h << 12) + (w << 2), srcb + (h << 5) + c4);
                }
        };

        if (tp) BARQ(barid);                          // quarter's bufs free before refill
        issue(0); CP_COMMIT();

        // B circular registers from pair table: w = (nf - T) & 7
        int bptr = GUARD + i0 + n0 + g - tg;
        uint32_t bv0[8], bv1[8];
        #pragma unroll
        for (int w = 0; w < 8; ++w)
            lds_pair(bv0[w], bv1[w], kpb + (uint32_t)((bptr + (w << 3)) << 3));

        float acc[2][8][4];
        #pragma unroll
        for (int mf = 0; mf < 2; ++mf)
            #pragma unroll
            for (int nf = 0; nf < 8; ++nf)
                #pragma unroll
                for (int r = 0; r < 4; ++r) acc[mf][nf][r] = 0.0f;

        for (int sc = 0; sc < nsc; ++sc) {
            CP_WAIT(0);                               // quarter's superchunk sc landed
            BARQ(barid);                              // visible to quarter; other stage free
            if (sc + 1 < nsc) { issue(sc + 1); }
            CP_COMMIT();

            const uint32_t bufb = qabase + (uint32_t)((sc & 1) ? STG_BYTES : 0);

            // software-pipelined A fragments: parity-indexed, zero-mov unrolled
            uint32_t a[2][2][4];
            {
                const int u0 = c0l;                   // T = 0 (col-half 0)
                ldsm_x4(a[0][0], bufb + (uint32_t)((rbase[0] + (u0 ^ swl[0])) << 2));
                ldsm_x4(a[0][1], bufb + (uint32_t)((rbase[1] + (u0 ^ swl[1])) << 2));
            }
            #pragma unroll
            for (int T = 0; T < 8; ++T) {
                const int p = T & 1;
                if (T < 7) {                          // prefetch T+1 fragments
                    const uint32_t hb = bufb + (uint32_t)((((T + 1) >> 2) & 1) << 12);
                    const int u = (((T + 1) & 3) << 3) | c0l;
                    ldsm_x4(a[p ^ 1][0], hb + (uint32_t)((rbase[0] + (u ^ swl[0])) << 2));
                    ldsm_x4(a[p ^ 1][1], hb + (uint32_t)((rbase[1] + (u ^ swl[1])) << 2));
                }
                #pragma unroll
                for (int nf = 0; nf < 8; ++nf) {
                    const int w = (nf - T) & 7;
                    mma_tf32(acc[0][nf], a[p][0], bv0[w], bv1[w]);
                    mma_tf32(acc[1][nf], a[p][1], bv0[w], bv1[w]);
                }
                const int wr = (7 - T) & 7;           // refill slot consumed 8 steps later
                lds_pair(bv0[wr], bv1[wr], kpb + (uint32_t)((bptr - 8) << 3));
                bptr -= 8;
            }
        }
        CP_WAIT(0);

        // ---- epilogue for this tile (quarter-local rows) ----
        #pragma unroll
        for (int mf = 0; mf < 2; ++mf) {
            const int row = b0 + (q << 5) + (mf << 4) + g;
            float* o0 = out + (size_t)row * FEAT + i0 + n0 + (tg << 1);
            float* o1 = o0 + 8 * FEAT;
            #pragma unroll
            for (int nf = 0; nf < 8; ++nf) {
                *(float2*)(o0 + (nf << 3)) = make_float2(acc[mf][nf][0], acc[mf][nf][1]);
                *(float2*)(o1 + (nf << 3)) = make_float2(acc[mf][nf][2], acc[mf][nf][3]);
            }
        }
    }
}

extern "C" void kernel_launch(void* const* d_in, const int* in_sizes, int n_in,
                              void* d_out, int out_size)
{
    const float* x    = (const float*)d_in[0];   // [2048, 4096] fp32
    const float* kern = (const float*)d_in[1];   // [4096] fp32
    float* out = (float*)d_out;                  // [2048, 4096] fp32

    cudaFuncSetAttribute(toep_mma9, cudaFuncAttributeMaxDynamicSharedMemorySize, SMEM_TOTAL);
    dim3 grid(16, 16);                           // 16 balanced tile-pairs x 16 batch tiles
    toep_mma9<<<grid, 256, SMEM_TOTAL>>>(x, kern, out);
}